// round 17
// baseline (speedup 1.0000x reference)
#include <cuda_runtime.h>
#include <cstdint>
#include <cstring>
#include <algorithm>

typedef unsigned int u32;
typedef unsigned long long u64;
typedef unsigned char u8;
typedef unsigned short u16;

#define U_SEGS   160000
#define TOPK     10
#define PSTRIDE  16                       // P board stride in u64 (128B: one L1 line per board)
#define TSTRIDE  16                       // T board stride in u32 (64B, aligned)
#define N_SAMPLED 48000                   // max(1, int(0.3 * 160000))
#define MASK_WORDS ((U_SEGS + 31) / 32)   // 5000 words = 20000 bytes
#define P2_BLOCKS 1184                    // 8 blocks/SM x 148 SMs: cheap drain when idle
#define P1_BLOCKS 740                     // 5 blocks/SM x 148 SMs: persistent phase 1

// ---------------- static device scratch (no runtime allocation) ----------------
__device__ __align__(128) u64 g_P[(size_t)U_SEGS * PSTRIDE];  // board by prediction, low32 = target bits
__device__ __align__(128) u32 g_T[(size_t)U_SEGS * TSTRIDE];  // board by target: key-only (IDCG is payload-free)
__device__ u64 g_thr2[U_SEGS];            // low32 = pred thr, high32 = targ thr
                                          // unsampled users: ~0 => gate auto-rejects (backstop)
__device__ u8  g_flag[U_SEGS];            // bit0: P needy, bit1: T needy (sampled users only)
__device__ u32 g_slist[N_SAMPLED];        // compact sampled-user list (deterministic, ordered)
__device__ int g_needy;                   // number of needy users after phase 1
__device__ int g_work;                    // phase-1 work-stealing chunk counter
__device__ u64 g_acc[2];                  // [0] fixed-point ndcg sum (x 2^32), [1] count
__device__ u32 g_done;                    // k_user completion counter (last block finalizes)

struct MaskParam { u32 w[MASK_WORDS]; };      // 20000 B by-value kernel param
struct PrefixParam { u16 p[MASK_WORDS]; };    // 10000 B: sampled-count prefix per mask word

__constant__ float c_w[TOPK] = {
    1.0f, 0.63092975f, 0.5f, 0.43067656f, 0.38685281f,
    0.35620719f, 0.33333334f, 0.31546488f, 0.30103f, 0.28906482f
};

// ---------------- threefry-2x32-20 (host + device) ----------------
__host__ __device__ __forceinline__ u32 rotl32(u32 v, int d) { return (v << d) | (v >> (32 - d)); }
__host__ __device__ inline void threefry2x32(u32 k0, u32 k1, u32 x0, u32 x1, u32& o0, u32& o1) {
    u32 ks2 = k0 ^ k1 ^ 0x1BD11BDAu;
    x0 += k0; x1 += k1;
#define TFR(r) { x0 += x1; x1 = rotl32(x1, (r)); x1 ^= x0; }
    TFR(13) TFR(15) TFR(26) TFR(6)
    x0 += k1;  x1 += ks2 + 1u;
    TFR(17) TFR(29) TFR(16) TFR(24)
    x0 += ks2; x1 += k0 + 2u;
    TFR(13) TFR(15) TFR(26) TFR(6)
    x0 += k0;  x1 += k1 + 3u;
    TFR(17) TFR(29) TFR(16) TFR(24)
    x0 += k1;  x1 += ks2 + 4u;
    TFR(13) TFR(15) TFR(26) TFR(6)
    x0 += ks2; x1 += k0 + 5u;
#undef TFR
    o0 = x0; o1 = x1;
}

__device__ __forceinline__ u32 ordf(float f) {
    u32 u = __float_as_uint(f);
    return (u & 0x80000000u) ? ~u : (u | 0x80000000u);
}
static inline u32 h_ordf(float f) {
    u32 u; memcpy(&u, &f, 4);
    return (u & 0x80000000u) ? ~u : (u | 0x80000000u);
}

// Unsorted top-10 boards via CAS on current min. All loads may be L1-stale: values only
// grow, so stale(min) <= current(min) -- skipping on stale is safe; a successful CAS pins
// the true current value, and all other slots' current >= stale >= evicted => the evicted
// value is the true board minimum => exact. Failed CAS learns the fresh value: progress.

// P board: u64 slots (hi = ordf(pred) key, lo = target-bits payload riding atomically).
// Ordering/argmin use ONLY the hi word (u32 ops): lo-order among hi-ties is in the
// accepted tie class (target-bits tiebreak). CAS still compares the full pinned u64.
__device__ __forceinline__ void tryInsertP(u64* b, u64 key, u32* thr, u32 thrSeen) {
    u64 v[TOPK]; u32 h[TOPK];
    const ulonglong2* b2 = reinterpret_cast<const ulonglong2*>(b);   // one 128B line
#pragma unroll
    for (int k = 0; k < TOPK / 2; k++) {
        ulonglong2 w = b2[k];
        v[2 * k] = w.x;                 v[2 * k + 1] = w.y;
        h[2 * k] = (u32)(w.x >> 32);    h[2 * k + 1] = (u32)(w.y >> 32);
    }
    u32 keyhi = (u32)(key >> 32);
    while (true) {
        u32 mh = h[0]; int am = 0;
#pragma unroll
        for (int s = 1; s < TOPK; s++) if (h[s] < mh) { mh = h[s]; am = s; }
        if (keyhi <= mh) {
            if (mh > thrSeen) atomicMax(thr, mh);
            return;
        }
        u64 old = atomicCAS(&b[am], v[am], key);
        if (old == v[am]) {
            u32 m2 = keyhi;
#pragma unroll
            for (int s = 0; s < TOPK; s++) if (s != am) m2 = min(m2, h[s]);
            if (m2 > thrSeen) atomicMax(thr, m2);
            return;
        }
        v[am] = old; h[am] = (u32)(old >> 32);
    }
}

// T board: u32 key-only slots. IDCG depends only on the multiset of top-10 target
// values, so ties need no stable payload -- equal keys are interchangeable. Exact.
__device__ __forceinline__ void tryInsertT(u32* b, u32 key, u32* thr, u32 thrSeen) {
    u32 v[TOPK];
    const uint4* b4 = reinterpret_cast<const uint4*>(b);
    uint4 w0 = b4[0], w1 = b4[1];
    uint2 w2 = reinterpret_cast<const uint2*>(b)[4];
    v[0] = w0.x; v[1] = w0.y; v[2] = w0.z; v[3] = w0.w;
    v[4] = w1.x; v[5] = w1.y; v[6] = w1.z; v[7] = w1.w;
    v[8] = w2.x; v[9] = w2.y;
    while (true) {
        u32 mn = v[0]; int am = 0;
#pragma unroll
        for (int s = 1; s < TOPK; s++) if (v[s] < mn) { mn = v[s]; am = s; }
        if (key <= mn) {
            if (mn > thrSeen) atomicMax(thr, mn);
            return;
        }
        u32 old = atomicCAS(&b[am], mn, key);
        if (old == mn) {
            u32 m2 = key;
#pragma unroll
            for (int s = 0; s < TOPK; s++) if (s != am) m2 = min(m2, v[s]);
            if (m2 > thrSeen) atomicMax(thr, m2);
            return;
        }
        v[am] = old;
    }
}

__device__ __forceinline__ void insertItem(int u, u32 op, u32 ot, float t,
                                           bool doP, bool doT, u64 tv) {
    if (doP && op >= (u32)tv)
        tryInsertP(&g_P[(size_t)u * PSTRIDE], ((u64)op << 32) | __float_as_uint(t),
                   (u32*)&g_thr2[u], (u32)tv);
    if (doT && ot >= (u32)(tv >> 32))
        tryInsertT(&g_T[(size_t)u * TSTRIDE], ot,
                   ((u32*)&g_thr2[u]) + 1, (u32)(tv >> 32));
}

// ---------------- kernels ----------------
// Fused init: thresholds (sampled open, unsampled ~0 backstop), sampled boards only
// (~5.8MB scattered vector stores), deterministic compact sampled list (prefix slots).
__global__ void k_init(MaskParam mp, PrefixParam pp) {
    int u = blockIdx.x * blockDim.x + threadIdx.x;
    if (u < 2) g_acc[u] = 0ull;
    if (u == 2) g_needy = 0;
    if (u == 3) g_done = 0u;
    if (u == 4) g_work = 0;
    if (u >= U_SEGS) return;
    u32 word = mp.w[u >> 5];
    bool samp = (word >> (u & 31)) & 1u;
    g_thr2[u] = samp ? 0ull : ~0ull;
    if (!samp) return;
    int slot = (int)pp.p[u >> 5] + __popc(word & ((1u << (u & 31)) - 1u));
    g_slist[slot] = (u32)u;
    ulonglong2* bp = reinterpret_cast<ulonglong2*>(&g_P[(size_t)u * PSTRIDE]);
    ulonglong2 z2; z2.x = 0ull; z2.y = 0ull;
#pragma unroll
    for (int k = 0; k < TOPK / 2; k++) bp[k] = z2;
    uint4* bt = reinterpret_cast<uint4*>(&g_T[(size_t)u * TSTRIDE]);
    uint4 z4; z4.x = z4.y = z4.z = z4.w = 0u;
    bt[0] = z4; bt[1] = z4;
    uint2* bt2 = reinterpret_cast<uint2*>(&g_T[(size_t)u * TSTRIDE]);
    uint2 z22; z22.x = z22.y = 0u;
    bt2[4] = z22;
}

// Tail items (n % 4): full thr-gated insert (no cutoff) -- exact on its own.
// Only launched when n % 4 != 0 (never for N = 16M).
__global__ void k_tail(const float* __restrict__ pred, const float* __restrict__ targ,
                       const int* __restrict__ idx, int start, int n) {
    if (blockIdx.x == 0 && threadIdx.x == 0) {
        for (int i = start; i < n; i++) {
            u32 op = ordf(pred[i]), ot = ordf(targ[i]);
            insertItem(idx[i], op, ot, targ[i], true, true, g_thr2[idx[i]]);
        }
    }
}

// Phase 1: items above global 60th-percentile cutoffs; thr gate (with unsampled
// backstop = ~0) filters to sampled users. PERSISTENT work-stealing grid: blocks
// pull 256-quad chunks off g_work, eliminating inter-wave imbalance and tail drain.
// Per-item work is bit-identical; ordering differences are covered by the
// CAS-monotone exactness proof. Inputs streamed evict-first (__ldcs).
__global__ void __launch_bounds__(256, 5)
k_phase1(const float4* __restrict__ pred4, const float4* __restrict__ targ4,
         const int4* __restrict__ idx4, int nq, int nchunks, float qpf, float qtf) {
    __shared__ int s_chunk;
    while (true) {
        if (threadIdx.x == 0) s_chunk = atomicAdd(&g_work, 1);
        __syncthreads();
        int chunk = s_chunk;
        __syncthreads();
        if (chunk >= nchunks) return;
        int q = chunk * 256 + threadIdx.x;
        if (q >= nq) continue;
        float4 pp = __ldcs(&pred4[q]);
        float4 tt = __ldcs(&targ4[q]);
        int4   uu = __ldcs(&idx4[q]);
        bool dp[4], dt[4], pass[4]; bool any = false;
#pragma unroll
        for (int j = 0; j < 4; j++) {
            dp[j] = (&pp.x)[j] >= qpf;    // float compare == ordf compare (no NaN in data)
            dt[j] = (&tt.x)[j] >= qtf;
            pass[j] = dp[j] | dt[j];
            any |= pass[j];
        }
        if (!any) continue;
        u64 tv[4];
#pragma unroll
        for (int j = 0; j < 4; j++)                   // batched: 4 outstanding thr loads
            tv[j] = pass[j] ? g_thr2[(&uu.x)[j]] : ~0ull;
#pragma unroll
        for (int j = 0; j < 4; j++) {
            if (pass[j])
                insertItem((&uu.x)[j], ordf((&pp.x)[j]), ordf((&tt.x)[j]), (&tt.x)[j],
                           dp[j], dt[j], tv[j]);
        }
    }
}

// Needy flags + global needy count. Unsampled users have thr=~0 => f=0 => never needy.
__global__ void k_flags() {
    int u = blockIdx.x * blockDim.x + threadIdx.x;
    u8 f = 0;
    if (u < U_SEGS) {
        u64 tv = g_thr2[u];
        f = (u8)((((u32)tv == 0u) ? 1u : 0u) | (((u32)(tv >> 32) == 0u) ? 2u : 0u));
        g_flag[u] = f;
    }
    u32 bal = __ballot_sync(0xFFFFFFFFu, f != 0);
    if ((threadIdx.x & 31) == 0 && bal)
        atomicAdd(&g_needy, __popc(bal));
}

// Phase 2 (exact fallback): below-cutoff items for needy (sampled) users only.
// PERSISTENT small grid: when needy==0 (always observed), 1184 blocks pay one
// L2-broadcast read and exit (~6us drain). When needy>0, grid-stride covers all quads.
__global__ void __launch_bounds__(256, 8)
k_phase2(const float4* __restrict__ pred4, const float4* __restrict__ targ4,
         const int4* __restrict__ idx4, int nq, u32 qp, u32 qt) {
    if (*(volatile int*)&g_needy == 0) return;
    int stride = gridDim.x * blockDim.x;
    for (int q = blockIdx.x * blockDim.x + threadIdx.x; q < nq; q += stride) {
        int4 uu = __ldcs(&idx4[q]);
        u8 f[4];
#pragma unroll
        for (int j = 0; j < 4; j++) f[j] = g_flag[(&uu.x)[j]];
        if (!(f[0] | f[1] | f[2] | f[3])) continue;
        float4 pp = __ldcs(&pred4[q]);
        float4 tt = __ldcs(&targ4[q]);
#pragma unroll
        for (int j = 0; j < 4; j++) {
            if (!f[j]) continue;
            u32 op = ordf((&pp.x)[j]), ot = ordf((&tt.x)[j]);
            bool dp = (f[j] & 1) && op < qp;
            bool dt = (f[j] & 2) && ot < qt;
            if (dp | dt)
                insertItem((&uu.x)[j], op, ot, (&tt.x)[j], dp, dt, g_thr2[(&uu.x)[j]]);
        }
    }
}

// Per-user NDCG over the compact sampled list (48k entries, no masking waste)
// + fixed-point reduction + last-block finalize.
__global__ void k_user(float* out) {
    __shared__ float sw[TOPK];
    __shared__ u64 ssum[256];
    __shared__ u32 scnt[256];
    if (threadIdx.x < TOPK) sw[threadIdx.x] = c_w[threadIdx.x];
    __syncthreads();
    int li = blockIdx.x * blockDim.x + threadIdx.x;
    u64 s = 0; u32 c = 0;
    if (li < N_SAMPLED) {
        int u = (int)g_slist[li];
        u64 a[TOPK]; u32 b[TOPK];
        const ulonglong2* pa = reinterpret_cast<const ulonglong2*>(&g_P[(size_t)u * PSTRIDE]);
#pragma unroll
        for (int k = 0; k < TOPK / 2; k++) {
            ulonglong2 wa = __ldg(&pa[k]); a[2 * k] = wa.x; a[2 * k + 1] = wa.y;
        }
        const uint4* pb = reinterpret_cast<const uint4*>(&g_T[(size_t)u * TSTRIDE]);
        uint4 w0 = __ldg(&pb[0]), w1 = __ldg(&pb[1]);
        uint2 w2 = __ldg(reinterpret_cast<const uint2*>(&g_T[(size_t)u * TSTRIDE]) + 4);
        b[0] = w0.x; b[1] = w0.y; b[2] = w0.z; b[3] = w0.w;
        b[4] = w1.x; b[5] = w1.y; b[6] = w1.z; b[7] = w1.w;
        b[8] = w2.x; b[9] = w2.y;
        float dcg = 0.f, idcg = 0.f;
        bool present = false;
#pragma unroll
        for (int i = 0; i < TOPK; i++) {
            if (a[i]) {
                present = true;
                int r = 0;
#pragma unroll
                for (int j = 0; j < TOPK; j++)
                    r += (a[j] > a[i]) || (a[j] == a[i] && j < i);
                dcg += sw[r] * __uint_as_float((u32)a[i]);
            }
            if (b[i]) {
                int r = 0;
#pragma unroll
                for (int j = 0; j < TOPK; j++)
                    r += (b[j] > b[i]) || (b[j] == b[i] && j < i);
                u32 o = b[i];
                u32 bits = (o & 0x80000000u) ? (o & 0x7FFFFFFFu) : ~o;  // decode ordf
                idcg += sw[r] * __uint_as_float(bits);
            }
        }
        if (present) {
            float nd = (idcg > 0.f) ? dcg / fmaxf(idcg, 1e-12f) : 0.f;
            s = (u64)((double)nd * 4294967296.0);
            c = 1;
        }
    }
    ssum[threadIdx.x] = s; scnt[threadIdx.x] = c;
    __syncthreads();
    for (int st = 128; st; st >>= 1) {
        if (threadIdx.x < st) { ssum[threadIdx.x] += ssum[threadIdx.x + st]; scnt[threadIdx.x] += scnt[threadIdx.x + st]; }
        __syncthreads();
    }
    if (threadIdx.x == 0) {
        if (ssum[0]) atomicAdd(&g_acc[0], ssum[0]);
        if (scnt[0]) atomicAdd(&g_acc[1], (u64)scnt[0]);
        __threadfence();
        u32 done = atomicAdd(&g_done, 1u);
        if (done == gridDim.x - 1) {                  // last block finalizes
            double sd = (double)g_acc[0] / 4294967296.0;
            double cd = (double)g_acc[1];
            out[0] = (float)(sd / (cd > 1.0 ? cd : 1.0));
        }
    }
}

// ---------------- host: exact permutation mask (data-independent => capture-time) ----------------
static void computeMask(MaskParam& mp, PrefixParam& pp) {
    static u32 keys[U_SEGS];
    static u32 vals[U_SEGS];
    static u32 tmpv[U_SEGS];
    static u32 ordr[U_SEGS];
    for (int i = 0; i < U_SEGS; i++) vals[i] = (u32)i;
    u32 kk0 = 0u, kk1 = 42u;
    for (int r = 0; r < 2; r++) {
        u32 nk0, nk1, sk0, sk1;
        threefry2x32(kk0, kk1, 0u, 0u, nk0, nk1);   // foldlike split: child 0 -> new key
        threefry2x32(kk0, kk1, 0u, 1u, sk0, sk1);   // child 1 -> subkey
        kk0 = nk0; kk1 = nk1;
        for (int i = 0; i < U_SEGS; i++) {
            u32 a, b;
            threefry2x32(sk0, sk1, 0u, (u32)i, a, b);
            keys[i] = a ^ b;
        }
        for (int i = 0; i < U_SEGS; i++) ordr[i] = (u32)i;
        std::stable_sort(ordr, ordr + U_SEGS,
                         [&](u32 x, u32 y) { return keys[x] < keys[y]; });
        for (int i = 0; i < U_SEGS; i++) tmpv[i] = vals[ordr[i]];
        memcpy(vals, tmpv, sizeof(tmpv));
    }
    memset(mp.w, 0, sizeof(mp.w));
    for (int i = 0; i < N_SAMPLED; i++) {
        u32 u = vals[i];
        mp.w[u >> 5] |= (1u << (u & 31));
    }
    int acc = 0;
    for (int w = 0; w < MASK_WORDS; w++) {
        pp.p[w] = (u16)acc;
        acc += __builtin_popcount(mp.w[w]);
    }
}

// ---------------- launch ----------------
extern "C" void kernel_launch(void* const* d_in, const int* in_sizes, int n_in,
                              void* d_out, int out_size) {
    const float* pred = (const float*)d_in[0];
    const float* targ = (const float*)d_in[1];
    const int*   idx  = (const int*)d_in[2];
    float* out = (float*)d_out;
    int n = in_sizes[0];

    static MaskParam mp;
    static PrefixParam pp;
    computeMask(mp, pp);                    // host-only, capture-time; deterministic constant

    const float QPF = 0.2533471f;           // invPhi(0.60), pred ~ N(0,1)
    const float QTF = 0.60f;                // 60th pct, targets ~ U(0,1)
    const u32 QP = h_ordf(QPF);
    const u32 QT = h_ordf(QTF);

    k_init<<<(U_SEGS + 255) / 256, 256>>>(mp, pp);   // 0

    int nq = n / 4;
    int nchunks = (nq + 255) / 256;
    if (nq > 0)
        k_phase1<<<P1_BLOCKS, 256>>>((const float4*)pred, (const float4*)targ,        // 1
                                     (const int4*)idx, nq, nchunks, QPF, QTF);
    if (n % 4)                              // capture-time constant; never for N = 16M
        k_tail<<<1, 32>>>(pred, targ, idx, nq * 4, n);
    k_flags<<<(U_SEGS + 511) / 512, 512>>>();                                          // 2
    if (nq > 0)
        k_phase2<<<P2_BLOCKS, 256>>>((const float4*)pred, (const float4*)targ,         // 3 <-- profiled
                                     (const int4*)idx, nq, QP, QT);
    k_user<<<(N_SAMPLED + 255) / 256, 256>>>(out);                                     // 4
}